// round 4
// baseline (speedup 1.0000x reference)
#include <cuda_runtime.h>
#include <cstdint>
#include <math.h>

#define BATCH 256
#define TSTEP 512
#define INDIM 64
#define HID   256
#define NCTA  128          // 64 clusters of 2 CTAs; cluster owns 4 batch rows

// Precomputed input projection, time-major: xw[t][b][h]
__device__ float g_xw[(size_t)TSTEP * BATCH * HID];

// Packed fp32x2 FMA (sm_100+)
__device__ __forceinline__ void fma2(float2& c, float2 a, float2 b) {
    asm("fma.rn.f32x2 %0, %1, %2, %0;"
        : "+l"(reinterpret_cast<unsigned long long&>(c))
        : "l"(reinterpret_cast<unsigned long long&>(a)),
          "l"(reinterpret_cast<unsigned long long&>(b)));
}

// Fast tanh: 1 - 2/(exp(2x)+1)
__device__ __forceinline__ float ftanh(float x) {
    float e = __expf(x + x);
    return 1.0f - __fdividef(2.0f, e + 1.0f);
}

// Acquire-cluster parity wait on a local mbarrier
__device__ __forceinline__ void mbar_wait(uint32_t mb, uint32_t ph) {
    uint32_t done;
    asm volatile(
        "{\n\t.reg .pred p;\n\t"
        "mbarrier.try_wait.parity.acquire.cluster.shared::cta.b64 p, [%1], %2;\n\t"
        "selp.b32 %0, 1, 0, p;\n\t}"
        : "=r"(done) : "r"(mb), "r"(ph) : "memory");
    while (!done) {
        asm volatile(
            "{\n\t.reg .pred p;\n\t"
            "mbarrier.try_wait.parity.acquire.cluster.shared::cta.b64 p, [%1], %2, 0x989680;\n\t"
            "selp.b32 %0, 1, 0, p;\n\t}"
            : "=r"(done) : "r"(mb), "r"(ph) : "memory");
    }
}

// ---------------------------------------------------------------------------
// Kernel 1: xw[t][b][h] = x[b][t][:] . W_ih[h][:] + b_ih[h] + b_hh[h]
// Grid: (B, T/32), block 256 (thread = h).
// ---------------------------------------------------------------------------
__global__ __launch_bounds__(256) void xw_kernel(
    const float* __restrict__ x, const float* __restrict__ W_ih,
    const float* __restrict__ b_ih, const float* __restrict__ b_hh)
{
    __shared__ float xs[32 * INDIM];
    const int b  = blockIdx.x;
    const int t0 = blockIdx.y * 32;
    const int h  = threadIdx.x;

    const float4* src = (const float4*)(x + ((size_t)b * TSTEP + t0) * INDIM);
    ((float4*)xs)[h]       = src[h];
    ((float4*)xs)[h + 256] = src[h + 256];

    float2 w[32];
    {
        const float4* wr = (const float4*)(W_ih + (size_t)h * INDIM);
        #pragma unroll
        for (int q = 0; q < 16; q++) {
            float4 v = wr[q];
            w[2*q]   = make_float2(v.x, v.y);
            w[2*q+1] = make_float2(v.z, v.w);
        }
    }
    const float bias = b_ih[h] + b_hh[h];
    __syncthreads();

    #pragma unroll 4
    for (int tt = 0; tt < 32; tt++) {
        float2 acc = make_float2(0.f, 0.f);
        #pragma unroll
        for (int q = 0; q < 16; q++) {
            float4 xv = ((const float4*)(xs + tt * INDIM))[q];
            fma2(acc, w[2*q],   make_float2(xv.x, xv.y));
            fma2(acc, w[2*q+1], make_float2(xv.z, xv.w));
        }
        g_xw[((size_t)(t0 + tt) * BATCH + b) * HID + h] = acc.x + acc.y + bias;
    }
}

// ---------------------------------------------------------------------------
// Kernel 2: the scan.
// 2-CTA clusters; CTA rank r owns W_hh rows [128r, 128r+128).
// Thread layout: 512 = 64 jg x 8 kq. Thread (jg,kq) owns j-cols {128r+jg,
// 128r+jg+64} over k in [32kq, 32kq+32): 64 W regs, h loads halved vs JT=1.
// Cluster owns 4 batch rows as 2 pipelined GROUPS of 2 rows, each with its own
// mbarrier (parity per step). Cross-CTA h exchange via DSMEM stores + one
// CTA-aggregated release.cluster arrive; peer data awaited with acquire
// try_wait, overlapped with the other group's compute.
// ---------------------------------------------------------------------------
__global__ void __cluster_dims__(2, 1, 1) __launch_bounds__(512, 1)
scan_kernel(const float* __restrict__ W_hh, const float* __restrict__ fc_W,
            const float* __restrict__ fc_b, float* __restrict__ out)
{
    __shared__ float hbuf[2][2][2][HID];   // [group][buf][row][h]  8KB
    __shared__ float part[2][8][128];      // [row][kq][j]          4KB (reused per group)
    __shared__ float fcw[HID];
    __shared__ __align__(8) unsigned long long mbar[2];

    const int tid = threadIdx.x;
    const int jg  = tid & 63;
    const int kq  = tid >> 6;              // 0..7
    const int cb  = (tid >> 7) & 1;        // combine row (tid<256)
    const int cjj = tid & 127;             // combine j within half
    uint32_t rank;
    asm("mov.u32 %0, %%cluster_ctarank;" : "=r"(rank));
    const uint32_t peer = rank ^ 1;
    const int cid = blockIdx.x >> 1;
    const int b0  = cid * 4;
    const int j1  = (int)rank * 128 + jg;
    const int j2  = j1 + 64;

    // ---- W_hh registers: 2 j-cols x 32 k = 64 floats
    float2 w0[16], w1[16];
    {
        const float4* r1 = (const float4*)(W_hh + (size_t)j1 * HID + kq * 32);
        const float4* r2 = (const float4*)(W_hh + (size_t)j2 * HID + kq * 32);
        #pragma unroll
        for (int q = 0; q < 8; q++) {
            float4 v = r1[q];
            w0[2*q]   = make_float2(v.x, v.y);
            w0[2*q+1] = make_float2(v.z, v.w);
        }
        #pragma unroll
        for (int q = 0; q < 8; q++) {
            float4 v = r2[q];
            w1[2*q]   = make_float2(v.x, v.y);
            w1[2*q+1] = make_float2(v.z, v.w);
        }
    }

    // ---- init: mbarriers (1024 arrivals/phase: 512 local + 512 remote),
    //      zero h buffers (buf 0), cache fc_W
    uint32_t mloc[2];
    mloc[0] = (uint32_t)__cvta_generic_to_shared(&mbar[0]);
    mloc[1] = (uint32_t)__cvta_generic_to_shared(&mbar[1]);
    if (tid == 0) {
        asm volatile("mbarrier.init.shared.b64 [%0], %1;" :: "r"(mloc[0]), "r"(1024) : "memory");
        asm volatile("mbarrier.init.shared.b64 [%0], %1;" :: "r"(mloc[1]), "r"(1024) : "memory");
    }
    for (int i = tid; i < 1024; i += 512) {
        int g = i >> 9, r = (i >> 8) & 1;
        hbuf[g][0][r][i & 255] = 0.f;
    }
    if (tid < HID) fcw[tid] = fc_W[tid];

    asm volatile("barrier.cluster.arrive.aligned;" ::: "memory");
    asm volatile("barrier.cluster.wait.aligned;"   ::: "memory");

    // ---- hoisted DSMEM addresses
    uint32_t hloc = (uint32_t)__cvta_generic_to_shared(&hbuf[0][0][0][0]);
    uint32_t hrem, mrem[2];
    asm("mapa.shared::cluster.u32 %0, %1, %2;" : "=r"(hrem)    : "r"(hloc),    "r"(peer));
    asm("mapa.shared::cluster.u32 %0, %1, %2;" : "=r"(mrem[0]) : "r"(mloc[0]), "r"(peer));
    asm("mapa.shared::cluster.u32 %0, %1, %2;" : "=r"(mrem[1]) : "r"(mloc[1]), "r"(peer));

    for (int t = 0; t < TSTEP; t++) {
        const int cur = t & 1;
        const int nxt = cur ^ 1;

        // prefetch xw additive terms for both groups (combine threads only)
        float xwp0 = 0.f, xwp1 = 0.f;
        if (tid < 256) {
            size_t base = ((size_t)t * BATCH + b0 + cb) * HID + (size_t)rank * 128 + cjj;
            xwp0 = g_xw[base];
            xwp1 = g_xw[base + 2 * HID];
        }

        #pragma unroll
        for (int g = 0; g < 2; g++) {
            if (t) mbar_wait(mloc[g], (uint32_t)((t - 1) & 1));

            // partial dot: 2 rows x 2 j-cols over this thread's 32 k
            const float4* hb0 = (const float4*)&hbuf[g][cur][0][kq * 32];
            const float4* hb1 = (const float4*)&hbuf[g][cur][1][kq * 32];
            float2 a00 = make_float2(0.f, 0.f), a01 = a00, a10 = a00, a11 = a00;
            #pragma unroll
            for (int q = 0; q < 8; q++) {
                float4 h0 = hb0[q];
                float4 h1 = hb1[q];
                float2 h0a = make_float2(h0.x, h0.y), h0b = make_float2(h0.z, h0.w);
                float2 h1a = make_float2(h1.x, h1.y), h1b = make_float2(h1.z, h1.w);
                fma2(a00, w0[2*q], h0a); fma2(a00, w0[2*q+1], h0b);
                fma2(a01, w1[2*q], h0a); fma2(a01, w1[2*q+1], h0b);
                fma2(a10, w0[2*q], h1a); fma2(a10, w0[2*q+1], h1b);
                fma2(a11, w1[2*q], h1a); fma2(a11, w1[2*q+1], h1b);
            }
            part[0][kq][jg]      = a00.x + a00.y;
            part[0][kq][jg + 64] = a01.x + a01.y;
            part[1][kq][jg]      = a10.x + a10.y;
            part[1][kq][jg + 64] = a11.x + a11.y;
            __syncthreads();

            // combine + tanh + write own & peer halves
            if (tid < 256) {
                float s = ((part[cb][0][cjj] + part[cb][1][cjj])
                         + (part[cb][2][cjj] + part[cb][3][cjj]))
                        + ((part[cb][4][cjj] + part[cb][5][cjj])
                         + (part[cb][6][cjj] + part[cb][7][cjj]))
                        + (g ? xwp1 : xwp0);
                float hv = ftanh(s);
                uint32_t off = (uint32_t)((((g * 2 + nxt) * 2 + cb) * HID
                                           + (int)rank * 128 + cjj) * 4);
                asm volatile("st.shared.f32 [%0], %1;"
                             :: "r"(hloc + off), "f"(hv) : "memory");
                asm volatile("st.shared::cluster.f32 [%0], %1;"
                             :: "r"(hrem + off), "f"(hv) : "memory");
            }
            __syncthreads();

            // CTA-aggregated arrivals (release.cluster covers all threads'
            // stores via the preceding __syncthreads + cumulativity)
            if (tid == 0) {
                asm volatile("mbarrier.arrive.release.cluster.shared::cta.b64 _, [%0], %1;"
                             :: "r"(mloc[g]), "r"(512) : "memory");
                asm volatile("mbarrier.arrive.release.cluster.shared::cluster.b64 _, [%0], %1;"
                             :: "r"(mrem[g]), "r"(512) : "memory");
            }
        }
    }

    // final h is in buf 0 (step 511 wrote nxt = 0); wait for phase 511 (parity 1)
    mbar_wait(mloc[0], 1u);
    mbar_wait(mloc[1], 1u);

    // fused FC on rank 0: out[b] = fc_W . h_last[b] + fc_b
    if (rank == 0) {
        const int wid = tid >> 5, lane = tid & 31;
        if (wid < 4) {
            const int g = wid >> 1, b = wid & 1;
            const float* hp = hbuf[g][0][b];
            float v = 0.f;
            #pragma unroll
            for (int i = 0; i < 8; i++)
                v += fcw[i * 32 + lane] * hp[i * 32 + lane];
            #pragma unroll
            for (int o = 16; o; o >>= 1) v += __shfl_down_sync(0xffffffffu, v, o);
            if (lane == 0) out[b0 + g * 2 + b] = v + fc_b[0];
        }
    }
}

// ---------------------------------------------------------------------------
extern "C" void kernel_launch(void* const* d_in, const int* in_sizes, int n_in,
                              void* d_out, int out_size)
{
    const float* x    = (const float*)d_in[0];
    const float* W_ih = (const float*)d_in[1];
    const float* W_hh = (const float*)d_in[2];
    const float* b_ih = (const float*)d_in[3];
    const float* b_hh = (const float*)d_in[4];
    const float* fc_W = (const float*)d_in[5];
    const float* fc_b = (const float*)d_in[6];
    float* out = (float*)d_out;

    xw_kernel<<<dim3(BATCH, TSTEP / 32), 256>>>(x, W_ih, b_ih, b_hh);
    scan_kernel<<<NCTA, 512>>>(W_hh, fc_W, fc_b, out);
}

// round 6
// speedup vs baseline: 1.2460x; 1.2460x over previous
#include <cuda_runtime.h>
#include <cstdint>
#include <math.h>

#define BATCH 256
#define TSTEP 512
#define INDIM 64
#define HID   256
#define NCTA  128          // 64 clusters of 2 CTAs; cluster owns 4 batch rows

// Precomputed input projection, time-major: xw[t][b][h]
__device__ float g_xw[(size_t)TSTEP * BATCH * HID];

// Packed fp32x2 FMA (sm_100+)
__device__ __forceinline__ void fma2(float2& c, float2 a, float2 b) {
    asm("fma.rn.f32x2 %0, %1, %2, %0;"
        : "+l"(reinterpret_cast<unsigned long long&>(c))
        : "l"(reinterpret_cast<unsigned long long&>(a)),
          "l"(reinterpret_cast<unsigned long long&>(b)));
}

// Fast tanh: 1 - 2/(exp(2x)+1)
__device__ __forceinline__ float ftanh(float x) {
    float e = __expf(x + x);
    return 1.0f - __fdividef(2.0f, e + 1.0f);
}

// Acquire-cluster parity wait on a local mbarrier
__device__ __forceinline__ void mbar_wait(uint32_t mb, uint32_t ph) {
    uint32_t done;
    asm volatile(
        "{\n\t.reg .pred p;\n\t"
        "mbarrier.try_wait.parity.acquire.cluster.shared::cta.b64 p, [%1], %2;\n\t"
        "selp.b32 %0, 1, 0, p;\n\t}"
        : "=r"(done) : "r"(mb), "r"(ph) : "memory");
    while (!done) {
        asm volatile(
            "{\n\t.reg .pred p;\n\t"
            "mbarrier.try_wait.parity.acquire.cluster.shared::cta.b64 p, [%1], %2, 0x989680;\n\t"
            "selp.b32 %0, 1, 0, p;\n\t}"
            : "=r"(done) : "r"(mb), "r"(ph) : "memory");
    }
}

// ---------------------------------------------------------------------------
// Kernel 1: xw[t][b][h] = x[b][t][:] . W_ih[h][:] + b_ih[h] + b_hh[h]
// Block 256 (thread = h, W_ih row in regs). 4 t processed concurrently with
// 4 independent accumulator chains.
// ---------------------------------------------------------------------------
__global__ __launch_bounds__(256) void xw_kernel(
    const float* __restrict__ x, const float* __restrict__ W_ih,
    const float* __restrict__ b_ih, const float* __restrict__ b_hh)
{
    __shared__ float xs[32 * INDIM];
    const int b  = blockIdx.x;
    const int t0 = blockIdx.y * 32;
    const int h  = threadIdx.x;

    const float4* src = (const float4*)(x + ((size_t)b * TSTEP + t0) * INDIM);
    ((float4*)xs)[h]       = src[h];
    ((float4*)xs)[h + 256] = src[h + 256];

    float2 w[32];
    {
        const float4* wr = (const float4*)(W_ih + (size_t)h * INDIM);
        #pragma unroll
        for (int q = 0; q < 16; q++) {
            float4 v = wr[q];
            w[2*q]   = make_float2(v.x, v.y);
            w[2*q+1] = make_float2(v.z, v.w);
        }
    }
    const float bias = b_ih[h] + b_hh[h];
    __syncthreads();

    for (int tt = 0; tt < 32; tt += 4) {
        float2 a0 = make_float2(0.f, 0.f), a1 = a0, a2 = a0, a3 = a0;
        #pragma unroll
        for (int q = 0; q < 16; q++) {
            float4 x0 = ((const float4*)(xs + (tt + 0) * INDIM))[q];
            float4 x1 = ((const float4*)(xs + (tt + 1) * INDIM))[q];
            float4 x2 = ((const float4*)(xs + (tt + 2) * INDIM))[q];
            float4 x3 = ((const float4*)(xs + (tt + 3) * INDIM))[q];
            fma2(a0, w[2*q], make_float2(x0.x, x0.y));
            fma2(a1, w[2*q], make_float2(x1.x, x1.y));
            fma2(a2, w[2*q], make_float2(x2.x, x2.y));
            fma2(a3, w[2*q], make_float2(x3.x, x3.y));
            fma2(a0, w[2*q+1], make_float2(x0.z, x0.w));
            fma2(a1, w[2*q+1], make_float2(x1.z, x1.w));
            fma2(a2, w[2*q+1], make_float2(x2.z, x2.w));
            fma2(a3, w[2*q+1], make_float2(x3.z, x3.w));
        }
        float* dst = &g_xw[((size_t)(t0 + tt) * BATCH + b) * HID + h];
        dst[0 * BATCH * HID] = a0.x + a0.y + bias;
        dst[1 * BATCH * HID] = a1.x + a1.y + bias;
        dst[2 * BATCH * HID] = a2.x + a2.y + bias;
        dst[3 * BATCH * HID] = a3.x + a3.y + bias;
    }
}

// ---------------------------------------------------------------------------
// Kernel 2: the scan, warp-specialized by k-half.
// 2-CTA clusters; CTA rank r finalizes j in [128r,128r+128) (== local k-half
// of next step). Thread (jg in 64, q in 8): j = {128r+jg, 128r+jg+64},
// k in [kbase, kbase+32) where q>=4 -> LOCAL k-half, q<4 -> PEER k-half.
//   tid>=256 (local k): released per step by combine's bar.arrive (cheap).
//   tid<256  (peer k):  released by peer CTA's DSMEM h stores + per-warp
//                       mbarrier release arrives (count 8).
// So the DSMEM exchange overlaps the local-half FMA work. One __syncthreads
// per step; partials double-buffered. Trailing cluster barrier before exit
// (exit-safety for in-flight remote DSMEM ops + visibility for the FC).
// ---------------------------------------------------------------------------
__global__ void __cluster_dims__(2, 1, 1) __launch_bounds__(512, 1)
scan_kernel(const float* __restrict__ W_hh, const float* __restrict__ fc_W,
            const float* __restrict__ fc_b, float* __restrict__ out)
{
    __shared__ float hbuf[2][4][HID];        // [buf][row][k]      8 KB
    __shared__ float part[2][4][8][128];     // [buf][row][q][j'] 16 KB
    __shared__ float fcw[HID];
    __shared__ __align__(8) unsigned long long mbar;

    const int tid = threadIdx.x;
    const int jg  = tid & 63;
    const int q   = tid >> 6;                // 0..7
    uint32_t rank;
    asm("mov.u32 %0, %%cluster_ctarank;" : "=r"(rank));
    const uint32_t peer = rank ^ 1;
    const int cid = blockIdx.x >> 1;
    const int b0  = cid * 4;
    const int j1  = (int)rank * 128 + jg;
    // k range: q>=4 -> own half, q<4 -> peer half
    const int kbase = ((q >= 4) ? (int)rank : (int)peer) * 128 + (q & 3) * 32;

    // ---- W_hh registers: 2 j-cols x 32 k
    float2 w0[16], w1[16];
    {
        const float4* r1 = (const float4*)(W_hh + (size_t)j1 * HID + kbase);
        const float4* r2 = (const float4*)(W_hh + (size_t)(j1 + 64) * HID + kbase);
        #pragma unroll
        for (int qq = 0; qq < 8; qq++) {
            float4 v = r1[qq];
            w0[2*qq]   = make_float2(v.x, v.y);
            w0[2*qq+1] = make_float2(v.z, v.w);
        }
        #pragma unroll
        for (int qq = 0; qq < 8; qq++) {
            float4 v = r2[qq];
            w1[2*qq]   = make_float2(v.x, v.y);
            w1[2*qq+1] = make_float2(v.z, v.w);
        }
    }

    // ---- init
    const uint32_t mloc = (uint32_t)__cvta_generic_to_shared(&mbar);
    if (tid == 0)
        asm volatile("mbarrier.init.shared.b64 [%0], %1;" :: "r"(mloc), "r"(8) : "memory");
    for (int i = tid; i < 4 * HID; i += 512) ((float*)hbuf[0])[i] = 0.f;
    if (tid < HID) fcw[tid] = fc_W[tid];

    asm volatile("barrier.cluster.arrive.aligned;" ::: "memory");
    asm volatile("barrier.cluster.wait.aligned;"   ::: "memory");

    const uint32_t hloc = (uint32_t)__cvta_generic_to_shared(&hbuf[0][0][0]);
    uint32_t hrem, mrem;
    asm("mapa.shared::cluster.u32 %0, %1, %2;" : "=r"(hrem) : "r"(hloc), "r"(peer));
    asm("mapa.shared::cluster.u32 %0, %1, %2;" : "=r"(mrem) : "r"(mloc), "r"(peer));

    // combine-role params (tid < 256)
    const int cb  = tid >> 7;                // rows cb and cb+2
    const int cjj = tid & 127;
    const int jc  = (int)rank * 128 + cjj;   // global j this thread finalizes

    for (int t = 0; t < TSTEP; t++) {
        const int cur = t & 1;
        const int nxt = cur ^ 1;

        float xw0 = 0.f, xw1 = 0.f;
        if (tid < 256) {                     // prefetch additive terms
            size_t base = ((size_t)t * BATCH + b0 + cb) * HID + jc;
            xw0 = g_xw[base];
            xw1 = g_xw[base + 2 * HID];
        }

        // wait for this thread's h inputs
        if (t) {
            if (tid < 256) mbar_wait(mloc, (uint32_t)((t - 1) & 1));  // peer half
            else asm volatile("bar.sync 1, 512;" ::: "memory");        // local half
        }

        // ---- partial dots: 4 rows x 2 j over this thread's 32 k
        const float4* hb = (const float4*)&hbuf[cur][0][kbase];  // row stride 64 float4
        float2 a00 = make_float2(0.f, 0.f), a01 = a00, a10 = a00, a11 = a00;
        float2 a20 = a00, a21 = a00, a30 = a00, a31 = a00;
        #pragma unroll
        for (int i = 0; i < 8; i++) {
            float4 h0 = hb[0 * 64 + i];
            float4 h1 = hb[1 * 64 + i];
            float4 h2 = hb[2 * 64 + i];
            float4 h3 = hb[3 * 64 + i];
            float2 h0a = make_float2(h0.x, h0.y), h0b = make_float2(h0.z, h0.w);
            float2 h1a = make_float2(h1.x, h1.y), h1b = make_float2(h1.z, h1.w);
            float2 h2a = make_float2(h2.x, h2.y), h2b = make_float2(h2.z, h2.w);
            float2 h3a = make_float2(h3.x, h3.y), h3b = make_float2(h3.z, h3.w);
            fma2(a00, w0[2*i], h0a); fma2(a00, w0[2*i+1], h0b);
            fma2(a01, w1[2*i], h0a); fma2(a01, w1[2*i+1], h0b);
            fma2(a10, w0[2*i], h1a); fma2(a10, w0[2*i+1], h1b);
            fma2(a11, w1[2*i], h1a); fma2(a11, w1[2*i+1], h1b);
            fma2(a20, w0[2*i], h2a); fma2(a20, w0[2*i+1], h2b);
            fma2(a21, w1[2*i], h2a); fma2(a21, w1[2*i+1], h2b);
            fma2(a30, w0[2*i], h3a); fma2(a30, w0[2*i+1], h3b);
            fma2(a31, w1[2*i], h3a); fma2(a31, w1[2*i+1], h3b);
        }
        part[cur][0][q][jg]      = a00.x + a00.y;
        part[cur][0][q][jg + 64] = a01.x + a01.y;
        part[cur][1][q][jg]      = a10.x + a10.y;
        part[cur][1][q][jg + 64] = a11.x + a11.y;
        part[cur][2][q][jg]      = a20.x + a20.y;
        part[cur][2][q][jg + 64] = a21.x + a21.y;
        part[cur][3][q][jg]      = a30.x + a30.y;
        part[cur][3][q][jg + 64] = a31.x + a31.y;
        __syncthreads();

        // ---- combine + tanh + local/remote h writes (tid < 256)
        if (tid < 256) {
            float s0 = ((part[cur][cb][0][cjj]   + part[cur][cb][1][cjj])
                      + (part[cur][cb][2][cjj]   + part[cur][cb][3][cjj]))
                     + ((part[cur][cb][4][cjj]   + part[cur][cb][5][cjj])
                      + (part[cur][cb][6][cjj]   + part[cur][cb][7][cjj])) + xw0;
            float s1 = ((part[cur][cb+2][0][cjj] + part[cur][cb+2][1][cjj])
                      + (part[cur][cb+2][2][cjj] + part[cur][cb+2][3][cjj]))
                     + ((part[cur][cb+2][4][cjj] + part[cur][cb+2][5][cjj])
                      + (part[cur][cb+2][6][cjj] + part[cur][cb+2][7][cjj])) + xw1;
            float hv0 = ftanh(s0);
            float hv1 = ftanh(s1);
            const uint32_t offA = (uint32_t)((((nxt * 4 + cb)     * HID) + jc) * 4);
            const uint32_t offB = (uint32_t)((((nxt * 4 + cb + 2) * HID) + jc) * 4);
            asm volatile("st.shared.f32 [%0], %1;" :: "r"(hloc + offA), "f"(hv0) : "memory");
            asm volatile("st.shared.f32 [%0], %1;" :: "r"(hloc + offB), "f"(hv1) : "memory");
            asm volatile("st.shared::cluster.f32 [%0], %1;" :: "r"(hrem + offA), "f"(hv0) : "memory");
            asm volatile("st.shared::cluster.f32 [%0], %1;" :: "r"(hrem + offB), "f"(hv1) : "memory");
            // release local-half readers (tid>=256) for next step
            asm volatile("bar.arrive 1, 512;" ::: "memory");
            // per-warp release arrive on the peer's mbarrier (8 arrivals/phase)
            __syncwarp();
            if ((tid & 31) == 0)
                asm volatile("mbarrier.arrive.release.cluster.shared::cluster.b64 _, [%0], 1;"
                             :: "r"(mrem) : "memory");
        }
    }

    // ---- exit safety + visibility: both CTAs release their final DSMEM
    // stores (arrive) and wait for the peer's (acquire) BEFORE anyone exits.
    __syncthreads();
    asm volatile("barrier.cluster.arrive.aligned;" ::: "memory");
    asm volatile("barrier.cluster.wait.aligned;"   ::: "memory");

    // final h_512 lives in hbuf[0] (t=511 wrote nxt=0); both halves visible now
    if (rank == 0 && tid < 128) {
        const int wid = tid >> 5, lane = tid & 31;
        const float* hp = hbuf[0][wid];
        float v = 0.f;
        #pragma unroll
        for (int i = 0; i < 8; i++)
            v += fcw[i * 32 + lane] * hp[i * 32 + lane];
        #pragma unroll
        for (int o = 16; o; o >>= 1) v += __shfl_down_sync(0xffffffffu, v, o);
        if (lane == 0) out[b0 + wid] = v + fc_b[0];
    }
}

// ---------------------------------------------------------------------------
extern "C" void kernel_launch(void* const* d_in, const int* in_sizes, int n_in,
                              void* d_out, int out_size)
{
    const float* x    = (const float*)d_in[0];
    const float* W_ih = (const float*)d_in[1];
    const float* W_hh = (const float*)d_in[2];
    const float* b_ih = (const float*)d_in[3];
    const float* b_hh = (const float*)d_in[4];
    const float* fc_W = (const float*)d_in[5];
    const float* fc_b = (const float*)d_in[6];
    float* out = (float*)d_out;

    xw_kernel<<<dim3(BATCH, TSTEP / 32), 256>>>(x, W_ih, b_ih, b_hh);
    scan_kernel<<<NCTA, 512>>>(W_hh, fc_W, fc_b, out);
}

// round 7
// speedup vs baseline: 1.3459x; 1.0801x over previous
#include <cuda_runtime.h>
#include <cstdint>
#include <math.h>

#define BATCH 256
#define TSTEP 512
#define INDIM 64
#define HID   256
#define NCTA  128          // 64 clusters of 2 CTAs; cluster owns 4 batch rows

// Precomputed input projection, time-major: xw[t][b][h]
__device__ float g_xw[(size_t)TSTEP * BATCH * HID];

// Packed fp32x2 FMA (sm_100+)
__device__ __forceinline__ void fma2(float2& c, float2 a, float2 b) {
    asm("fma.rn.f32x2 %0, %1, %2, %0;"
        : "+l"(reinterpret_cast<unsigned long long&>(c))
        : "l"(reinterpret_cast<unsigned long long&>(a)),
          "l"(reinterpret_cast<unsigned long long&>(b)));
}

// HW tanh (MUFU.TANH, sm_75+)
__device__ __forceinline__ float htanh(float x) {
    float y;
    asm("tanh.approx.f32 %0, %1;" : "=f"(y) : "f"(x));
    return y;
}

// Acquire-cluster parity wait on a local mbarrier
__device__ __forceinline__ void mbar_wait(uint32_t mb, uint32_t ph) {
    uint32_t done;
    asm volatile(
        "{\n\t.reg .pred p;\n\t"
        "mbarrier.try_wait.parity.acquire.cluster.shared::cta.b64 p, [%1], %2;\n\t"
        "selp.b32 %0, 1, 0, p;\n\t}"
        : "=r"(done) : "r"(mb), "r"(ph) : "memory");
    while (!done) {
        asm volatile(
            "{\n\t.reg .pred p;\n\t"
            "mbarrier.try_wait.parity.acquire.cluster.shared::cta.b64 p, [%1], %2, 0x989680;\n\t"
            "selp.b32 %0, 1, 0, p;\n\t}"
            : "=r"(done) : "r"(mb), "r"(ph) : "memory");
    }
}

// ---------------------------------------------------------------------------
// Kernel 1: xw[t][b][h] = x[b][t][:] . W_ih[h][:] + b_ih[h] + b_hh[h]
// Block 256 (thread = h, W_ih row in regs). 8 t processed concurrently with
// 8 independent accumulator chains for ILP.
// ---------------------------------------------------------------------------
__global__ __launch_bounds__(256) void xw_kernel(
    const float* __restrict__ x, const float* __restrict__ W_ih,
    const float* __restrict__ b_ih, const float* __restrict__ b_hh)
{
    __shared__ float xs[32 * INDIM];
    const int b  = blockIdx.x;
    const int t0 = blockIdx.y * 32;
    const int h  = threadIdx.x;

    const float4* src = (const float4*)(x + ((size_t)b * TSTEP + t0) * INDIM);
    ((float4*)xs)[h]       = src[h];
    ((float4*)xs)[h + 256] = src[h + 256];

    float2 w[32];
    {
        const float4* wr = (const float4*)(W_ih + (size_t)h * INDIM);
        #pragma unroll
        for (int q = 0; q < 16; q++) {
            float4 v = wr[q];
            w[2*q]   = make_float2(v.x, v.y);
            w[2*q+1] = make_float2(v.z, v.w);
        }
    }
    const float bias = b_ih[h] + b_hh[h];
    __syncthreads();

    for (int tt = 0; tt < 32; tt += 8) {
        float2 a[8];
        #pragma unroll
        for (int u = 0; u < 8; u++) a[u] = make_float2(0.f, 0.f);
        #pragma unroll
        for (int q = 0; q < 16; q++) {
            #pragma unroll
            for (int u = 0; u < 8; u++) {
                float4 xv = ((const float4*)(xs + (tt + u) * INDIM))[q];
                fma2(a[u], w[2*q],   make_float2(xv.x, xv.y));
                fma2(a[u], w[2*q+1], make_float2(xv.z, xv.w));
            }
        }
        float* dst = &g_xw[((size_t)(t0 + tt) * BATCH + b) * HID + h];
        #pragma unroll
        for (int u = 0; u < 8; u++)
            dst[(size_t)u * BATCH * HID] = a[u].x + a[u].y + bias;
    }
}

// ---------------------------------------------------------------------------
// Kernel 2: the scan, warp-specialized by k-half.
// 2-CTA clusters; CTA rank r finalizes j in [128r,128r+128) (== local k-half
// of next step). Thread (jg in 64, q in 8): j = {128r+jg, 128r+jg+64},
// k in [kbase, kbase+32) where q>=4 -> LOCAL k-half, q<4 -> PEER k-half.
//   tid>=256 (local k): proceed straight from the post-combine __syncthreads.
//   tid<256  (peer k):  additionally gated by the peer's mbarrier (count 16,
//                       per-warp release arrives after the DSMEM h stores).
// Combine distributed over ALL 512 threads (1 element each) + HW tanh.
// ---------------------------------------------------------------------------
__global__ void __cluster_dims__(2, 1, 1) __launch_bounds__(512, 1)
scan_kernel(const float* __restrict__ W_hh, const float* __restrict__ fc_W,
            const float* __restrict__ fc_b, float* __restrict__ out)
{
    __shared__ float hbuf[2][4][HID];        // [buf][row][k]     8 KB
    __shared__ float part[4][8][128];        // [row][q][j']      16 KB
    __shared__ float fcw[HID];
    __shared__ __align__(8) unsigned long long mbar;

    const int tid = threadIdx.x;
    const int jg  = tid & 63;
    const int q   = tid >> 6;                // 0..7
    uint32_t rank;
    asm("mov.u32 %0, %%cluster_ctarank;" : "=r"(rank));
    const uint32_t peer = rank ^ 1;
    const int cid = blockIdx.x >> 1;
    const int b0  = cid * 4;
    const int j1  = (int)rank * 128 + jg;
    // k range: q>=4 -> own half, q<4 -> peer half
    const int kbase = ((q >= 4) ? (int)rank : (int)peer) * 128 + (q & 3) * 32;

    // ---- W_hh registers: 2 j-cols x 32 k
    float2 w0[16], w1[16];
    {
        const float4* r1 = (const float4*)(W_hh + (size_t)j1 * HID + kbase);
        const float4* r2 = (const float4*)(W_hh + (size_t)(j1 + 64) * HID + kbase);
        #pragma unroll
        for (int qq = 0; qq < 8; qq++) {
            float4 v = r1[qq];
            w0[2*qq]   = make_float2(v.x, v.y);
            w0[2*qq+1] = make_float2(v.z, v.w);
        }
        #pragma unroll
        for (int qq = 0; qq < 8; qq++) {
            float4 v = r2[qq];
            w1[2*qq]   = make_float2(v.x, v.y);
            w1[2*qq+1] = make_float2(v.z, v.w);
        }
    }

    // ---- init
    const uint32_t mloc = (uint32_t)__cvta_generic_to_shared(&mbar);
    if (tid == 0)
        asm volatile("mbarrier.init.shared.b64 [%0], %1;" :: "r"(mloc), "r"(16) : "memory");
    for (int i = tid; i < 4 * HID; i += 512) ((float*)hbuf[0])[i] = 0.f;
    if (tid < HID) fcw[tid] = fc_W[tid];

    asm volatile("barrier.cluster.arrive.aligned;" ::: "memory");
    asm volatile("barrier.cluster.wait.aligned;"   ::: "memory");

    const uint32_t hloc = (uint32_t)__cvta_generic_to_shared(&hbuf[0][0][0]);
    uint32_t hrem, mrem;
    asm("mapa.shared::cluster.u32 %0, %1, %2;" : "=r"(hrem) : "r"(hloc), "r"(peer));
    asm("mapa.shared::cluster.u32 %0, %1, %2;" : "=r"(mrem) : "r"(mloc), "r"(peer));

    // combine-role params: every thread finalizes ONE (row, j) element
    const int crow = tid >> 7;               // 0..3
    const int cjj  = tid & 127;
    const int jc   = (int)rank * 128 + cjj;  // global j this thread finalizes

    for (int t = 0; t < TSTEP; t++) {
        const int cur = t & 1;
        const int nxt = cur ^ 1;

        // prefetch additive term (one per thread)
        const float xw = g_xw[((size_t)t * BATCH + b0 + crow) * HID + jc];

        // peer-k threads wait for peer's h half of this step
        if (t && tid < 256) mbar_wait(mloc, (uint32_t)((t - 1) & 1));

        // ---- partial dots: 4 rows x 2 j over this thread's 32 k
        const float4* hb = (const float4*)&hbuf[cur][0][kbase];  // row stride 64 float4
        float2 a00 = make_float2(0.f, 0.f), a01 = a00, a10 = a00, a11 = a00;
        float2 a20 = a00, a21 = a00, a30 = a00, a31 = a00;
        #pragma unroll
        for (int i = 0; i < 8; i++) {
            float4 h0 = hb[0 * 64 + i];
            float4 h1 = hb[1 * 64 + i];
            float4 h2 = hb[2 * 64 + i];
            float4 h3 = hb[3 * 64 + i];
            float2 h0a = make_float2(h0.x, h0.y), h0b = make_float2(h0.z, h0.w);
            float2 h1a = make_float2(h1.x, h1.y), h1b = make_float2(h1.z, h1.w);
            float2 h2a = make_float2(h2.x, h2.y), h2b = make_float2(h2.z, h2.w);
            float2 h3a = make_float2(h3.x, h3.y), h3b = make_float2(h3.z, h3.w);
            fma2(a00, w0[2*i], h0a); fma2(a00, w0[2*i+1], h0b);
            fma2(a01, w1[2*i], h0a); fma2(a01, w1[2*i+1], h0b);
            fma2(a10, w0[2*i], h1a); fma2(a10, w0[2*i+1], h1b);
            fma2(a11, w1[2*i], h1a); fma2(a11, w1[2*i+1], h1b);
            fma2(a20, w0[2*i], h2a); fma2(a20, w0[2*i+1], h2b);
            fma2(a21, w1[2*i], h2a); fma2(a21, w1[2*i+1], h2b);
            fma2(a30, w0[2*i], h3a); fma2(a30, w0[2*i+1], h3b);
            fma2(a31, w1[2*i], h3a); fma2(a31, w1[2*i+1], h3b);
        }
        part[0][q][jg]      = a00.x + a00.y;
        part[0][q][jg + 64] = a01.x + a01.y;
        part[1][q][jg]      = a10.x + a10.y;
        part[1][q][jg + 64] = a11.x + a11.y;
        part[2][q][jg]      = a20.x + a20.y;
        part[2][q][jg + 64] = a21.x + a21.y;
        part[3][q][jg]      = a30.x + a30.y;
        part[3][q][jg + 64] = a31.x + a31.y;
        __syncthreads();

        // ---- combine + tanh + local/remote h write: 1 element per thread
        {
            float s = ((part[crow][0][cjj] + part[crow][1][cjj])
                     + (part[crow][2][cjj] + part[crow][3][cjj]))
                    + ((part[crow][4][cjj] + part[crow][5][cjj])
                     + (part[crow][6][cjj] + part[crow][7][cjj])) + xw;
            float hv = htanh(s);
            const uint32_t off = (uint32_t)((((nxt * 4 + crow) * HID) + jc) * 4);
            asm volatile("st.shared.f32 [%0], %1;" :: "r"(hloc + off), "f"(hv) : "memory");
            asm volatile("st.shared::cluster.f32 [%0], %1;" :: "r"(hrem + off), "f"(hv) : "memory");
        }
        __syncthreads();   // h local visible; part reads done before next STS

        // per-warp release arrive on the peer's mbarrier (16 arrivals/phase);
        // each warp's DSMEM stores precede its arrive in program order.
        if ((tid & 31) == 0)
            asm volatile("mbarrier.arrive.release.cluster.shared::cluster.b64 _, [%0], 1;"
                         :: "r"(mrem) : "memory");
    }

    // ---- exit safety + visibility: both CTAs release their final DSMEM
    // stores (arrive) and wait for the peer's (acquire) BEFORE anyone exits.
    asm volatile("barrier.cluster.arrive.aligned;" ::: "memory");
    asm volatile("barrier.cluster.wait.aligned;"   ::: "memory");

    // final h_512 lives in hbuf[0] (t=511 wrote nxt=0); both halves visible now
    if (rank == 0 && tid < 128) {
        const int wid = tid >> 5, lane = tid & 31;
        const float* hp = hbuf[0][wid];
        float v = 0.f;
        #pragma unroll
        for (int i = 0; i < 8; i++)
            v += fcw[i * 32 + lane] * hp[i * 32 + lane];
        #pragma unroll
        for (int o = 16; o; o >>= 1) v += __shfl_down_sync(0xffffffffu, v, o);
        if (lane == 0) out[b0 + wid] = v + fc_b[0];
    }
}

// ---------------------------------------------------------------------------
extern "C" void kernel_launch(void* const* d_in, const int* in_sizes, int n_in,
                              void* d_out, int out_size)
{
    const float* x    = (const float*)d_in[0];
    const float* W_ih = (const float*)d_in[1];
    const float* W_hh = (const float*)d_in[2];
    const float* b_ih = (const float*)d_in[3];
    const float* b_hh = (const float*)d_in[4];
    const float* fc_W = (const float*)d_in[5];
    const float* fc_b = (const float*)d_in[6];
    float* out = (float*)d_out;

    xw_kernel<<<dim3(BATCH, TSTEP / 32), 256>>>(x, W_ih, b_ih, b_hh);
    scan_kernel<<<NCTA, 512>>>(W_hh, fc_W, fc_b, out);
}

// round 8
// speedup vs baseline: 1.7285x; 1.2843x over previous
#include <cuda_runtime.h>
#include <cstdint>
#include <math.h>

#define BATCH 256
#define TSTEP 512
#define INDIM 64
#define HID   256
#define NCTA  128          // 64 clusters of 2 CTAs; cluster owns 4 batch rows

// Precomputed input projection, time-major: xw[t][b][h]
__device__ float g_xw[(size_t)TSTEP * BATCH * HID];

// Packed fp32x2 FMA (sm_100+)
__device__ __forceinline__ void fma2(float2& c, float2 a, float2 b) {
    asm("fma.rn.f32x2 %0, %1, %2, %0;"
        : "+l"(reinterpret_cast<unsigned long long&>(c))
        : "l"(reinterpret_cast<unsigned long long&>(a)),
          "l"(reinterpret_cast<unsigned long long&>(b)));
}

// HW tanh (MUFU.TANH, sm_75+)
__device__ __forceinline__ float htanh(float x) {
    float y;
    asm("tanh.approx.f32 %0, %1;" : "=f"(y) : "f"(x));
    return y;
}

// Acquire-cluster parity wait on a local mbarrier
__device__ __forceinline__ void mbar_wait(uint32_t mb, uint32_t ph) {
    uint32_t done;
    asm volatile(
        "{\n\t.reg .pred p;\n\t"
        "mbarrier.try_wait.parity.acquire.cluster.shared::cta.b64 p, [%1], %2;\n\t"
        "selp.b32 %0, 1, 0, p;\n\t}"
        : "=r"(done) : "r"(mb), "r"(ph) : "memory");
    while (!done) {
        asm volatile(
            "{\n\t.reg .pred p;\n\t"
            "mbarrier.try_wait.parity.acquire.cluster.shared::cta.b64 p, [%1], %2, 0x989680;\n\t"
            "selp.b32 %0, 1, 0, p;\n\t}"
            : "=r"(done) : "r"(mb), "r"(ph) : "memory");
    }
}

// ---------------------------------------------------------------------------
// Kernel 1: xw[t][b][h] = x[b][t][:] . W_ih[h][:] + b_ih[h] + b_hh[h]
// Block 256 (thread = h, W_ih row in regs), 4 batch rows x 32 t per block:
// W_ih register load amortized over 128 outputs/thread; 8 independent
// accumulator chains for ILP.
// ---------------------------------------------------------------------------
__global__ __launch_bounds__(256) void xw_kernel(
    const float* __restrict__ x, const float* __restrict__ W_ih,
    const float* __restrict__ b_ih, const float* __restrict__ b_hh)
{
    __shared__ float xs[4][32 * INDIM];     // 32 KB
    const int b0 = blockIdx.x * 4;
    const int t0 = blockIdx.y * 32;
    const int h  = threadIdx.x;

    #pragma unroll
    for (int bb = 0; bb < 4; bb++) {
        const float4* src = (const float4*)(x + ((size_t)(b0 + bb) * TSTEP + t0) * INDIM);
        ((float4*)xs[bb])[h]       = src[h];
        ((float4*)xs[bb])[h + 256] = src[h + 256];
    }

    float2 w[32];
    {
        const float4* wr = (const float4*)(W_ih + (size_t)h * INDIM);
        #pragma unroll
        for (int q = 0; q < 16; q++) {
            float4 v = wr[q];
            w[2*q]   = make_float2(v.x, v.y);
            w[2*q+1] = make_float2(v.z, v.w);
        }
    }
    const float bias = b_ih[h] + b_hh[h];
    __syncthreads();

    for (int bb = 0; bb < 4; bb++) {
        for (int tt = 0; tt < 32; tt += 8) {
            float2 a[8];
            #pragma unroll
            for (int u = 0; u < 8; u++) a[u] = make_float2(0.f, 0.f);
            #pragma unroll
            for (int q = 0; q < 16; q++) {
                #pragma unroll
                for (int u = 0; u < 8; u++) {
                    float4 xv = ((const float4*)(xs[bb] + (tt + u) * INDIM))[q];
                    fma2(a[u], w[2*q],   make_float2(xv.x, xv.y));
                    fma2(a[u], w[2*q+1], make_float2(xv.z, xv.w));
                }
            }
            float* dst = &g_xw[((size_t)(t0 + tt) * BATCH + b0 + bb) * HID + h];
            #pragma unroll
            for (int u = 0; u < 8; u++)
                dst[(size_t)u * BATCH * HID] = a[u].x + a[u].y + bias;
        }
    }
}

// ---------------------------------------------------------------------------
// Kernel 2: the scan, warp-specialized by k-half, ASYNC cross-CTA push.
// 2-CTA clusters; CTA rank r finalizes j in [128r,128r+128) (== local k-half
// of next step). Thread (jg in 64, q in 8): j = {128r+jg, 128r+jg+64},
// k in [kbase, kbase+32) where q>=4 -> LOCAL k-half, q<4 -> PEER k-half.
// Cross-CTA h exchange: per-thread st.async with mbarrier complete_tx into
// the peer's smem (fire-and-forget; NO release fences, NO per-warp arrives).
// Peer mbarrier phase = 2048 tx bytes + tid0's arrive.expect_tx (count=1).
// ---------------------------------------------------------------------------
__global__ void __cluster_dims__(2, 1, 1) __launch_bounds__(512, 1)
scan_kernel(const float* __restrict__ W_hh, const float* __restrict__ fc_W,
            const float* __restrict__ fc_b, float* __restrict__ out)
{
    __shared__ float hbuf[2][4][HID];        // [buf][row][k]     8 KB
    __shared__ float part[4][8][128];        // [row][q][j']      16 KB
    __shared__ float fcw[HID];
    __shared__ __align__(8) unsigned long long mbar;

    const int tid = threadIdx.x;
    const int jg  = tid & 63;
    const int q   = tid >> 6;                // 0..7
    uint32_t rank;
    asm("mov.u32 %0, %%cluster_ctarank;" : "=r"(rank));
    const uint32_t peer = rank ^ 1;
    const int cid = blockIdx.x >> 1;
    const int b0  = cid * 4;
    const int j1  = (int)rank * 128 + jg;
    // k range: q>=4 -> own half, q<4 -> peer half
    const int kbase = ((q >= 4) ? (int)rank : (int)peer) * 128 + (q & 3) * 32;

    // ---- W_hh registers: 2 j-cols x 32 k
    float2 w0[16], w1[16];
    {
        const float4* r1 = (const float4*)(W_hh + (size_t)j1 * HID + kbase);
        const float4* r2 = (const float4*)(W_hh + (size_t)(j1 + 64) * HID + kbase);
        #pragma unroll
        for (int qq = 0; qq < 8; qq++) {
            float4 v = r1[qq];
            w0[2*qq]   = make_float2(v.x, v.y);
            w0[2*qq+1] = make_float2(v.z, v.w);
        }
        #pragma unroll
        for (int qq = 0; qq < 8; qq++) {
            float4 v = r2[qq];
            w1[2*qq]   = make_float2(v.x, v.y);
            w1[2*qq+1] = make_float2(v.z, v.w);
        }
    }

    // ---- init (mbar count=1: only tid0's arrive.expect_tx per phase)
    const uint32_t mloc = (uint32_t)__cvta_generic_to_shared(&mbar);
    if (tid == 0)
        asm volatile("mbarrier.init.shared.b64 [%0], %1;" :: "r"(mloc), "r"(1) : "memory");
    for (int i = tid; i < 4 * HID; i += 512) ((float*)hbuf[0])[i] = 0.f;
    if (tid < HID) fcw[tid] = fc_W[tid];

    asm volatile("barrier.cluster.arrive.aligned;" ::: "memory");
    asm volatile("barrier.cluster.wait.aligned;"   ::: "memory");

    const uint32_t hloc = (uint32_t)__cvta_generic_to_shared(&hbuf[0][0][0]);
    uint32_t hrem, mrem;
    asm("mapa.shared::cluster.u32 %0, %1, %2;" : "=r"(hrem) : "r"(hloc), "r"(peer));
    asm("mapa.shared::cluster.u32 %0, %1, %2;" : "=r"(mrem) : "r"(mloc), "r"(peer));

    // combine-role params: every thread finalizes ONE (row, j) element
    const int crow = tid >> 7;               // 0..3
    const int cjj  = tid & 127;
    const int jc   = (int)rank * 128 + cjj;  // global j this thread finalizes

    for (int t = 0; t < TSTEP; t++) {
        const int cur = t & 1;
        const int nxt = cur ^ 1;

        // prefetch additive term (one per thread)
        const float xw = g_xw[((size_t)t * BATCH + b0 + crow) * HID + jc];

        // peer-k threads wait for peer's h half of this step (phase t-1)
        if (t && tid < 256) mbar_wait(mloc, (uint32_t)((t - 1) & 1));
        // tid0: fund phase t (gates step t+1): 1 arrival + 2048 expected bytes
        if (tid == 0)
            asm volatile("mbarrier.arrive.expect_tx.shared.b64 _, [%0], %1;"
                         :: "r"(mloc), "r"(2048) : "memory");

        // ---- partial dots: 4 rows x 2 j over this thread's 32 k
        const float4* hb = (const float4*)&hbuf[cur][0][kbase];  // row stride 64 float4
        float2 a00 = make_float2(0.f, 0.f), a01 = a00, a10 = a00, a11 = a00;
        float2 a20 = a00, a21 = a00, a30 = a00, a31 = a00;
        #pragma unroll
        for (int i = 0; i < 8; i++) {
            float4 h0 = hb[0 * 64 + i];
            float4 h1 = hb[1 * 64 + i];
            float4 h2 = hb[2 * 64 + i];
            float4 h3 = hb[3 * 64 + i];
            float2 h0a = make_float2(h0.x, h0.y), h0b = make_float2(h0.z, h0.w);
            float2 h1a = make_float2(h1.x, h1.y), h1b = make_float2(h1.z, h1.w);
            float2 h2a = make_float2(h2.x, h2.y), h2b = make_float2(h2.z, h2.w);
            float2 h3a = make_float2(h3.x, h3.y), h3b = make_float2(h3.z, h3.w);
            fma2(a00, w0[2*i], h0a); fma2(a00, w0[2*i+1], h0b);
            fma2(a01, w1[2*i], h0a); fma2(a01, w1[2*i+1], h0b);
            fma2(a10, w0[2*i], h1a); fma2(a10, w0[2*i+1], h1b);
            fma2(a11, w1[2*i], h1a); fma2(a11, w1[2*i+1], h1b);
            fma2(a20, w0[2*i], h2a); fma2(a20, w0[2*i+1], h2b);
            fma2(a21, w1[2*i], h2a); fma2(a21, w1[2*i+1], h2b);
            fma2(a30, w0[2*i], h3a); fma2(a30, w0[2*i+1], h3b);
            fma2(a31, w1[2*i], h3a); fma2(a31, w1[2*i+1], h3b);
        }
        part[0][q][jg]      = a00.x + a00.y;
        part[0][q][jg + 64] = a01.x + a01.y;
        part[1][q][jg]      = a10.x + a10.y;
        part[1][q][jg + 64] = a11.x + a11.y;
        part[2][q][jg]      = a20.x + a20.y;
        part[2][q][jg + 64] = a21.x + a21.y;
        part[3][q][jg]      = a30.x + a30.y;
        part[3][q][jg + 64] = a31.x + a31.y;
        __syncthreads();

        // ---- combine + tanh + local store + ASYNC remote push (1 elt/thread)
        {
            float s = ((part[crow][0][cjj] + part[crow][1][cjj])
                     + (part[crow][2][cjj] + part[crow][3][cjj]))
                    + ((part[crow][4][cjj] + part[crow][5][cjj])
                     + (part[crow][6][cjj] + part[crow][7][cjj])) + xw;
            float hv = htanh(s);
            const uint32_t off = (uint32_t)((((nxt * 4 + crow) * HID) + jc) * 4);
            asm volatile("st.shared.f32 [%0], %1;" :: "r"(hloc + off), "f"(hv) : "memory");
            asm volatile(
                "st.async.weak.shared::cluster.mbarrier::complete_tx::bytes.b32 [%0], %1, [%2];"
                :: "r"(hrem + off), "r"(__float_as_uint(hv)), "r"(mrem) : "memory");
        }
        __syncthreads();   // local h visible; part reads done before next STS
    }

    // drain phase 511 (parity 1): peer's final st.async landed in our smem
    if (tid < 256) mbar_wait(mloc, 1u);
    __syncthreads();
    // exit safety: no CTA leaves while its st.async into the peer may be in flight
    asm volatile("barrier.cluster.arrive.aligned;" ::: "memory");
    asm volatile("barrier.cluster.wait.aligned;"   ::: "memory");

    // final h_512 lives in hbuf[0] (t=511 wrote nxt=0)
    if (rank == 0 && tid < 128) {
        const int wid = tid >> 5, lane = tid & 31;
        const float* hp = hbuf[0][wid];
        float v = 0.f;
        #pragma unroll
        for (int i = 0; i < 8; i++)
            v += fcw[i * 32 + lane] * hp[i * 32 + lane];
        #pragma unroll
        for (int o = 16; o; o >>= 1) v += __shfl_down_sync(0xffffffffu, v, o);
        if (lane == 0) out[b0 + wid] = v + fc_b[0];
    }
}

// ---------------------------------------------------------------------------
extern "C" void kernel_launch(void* const* d_in, const int* in_sizes, int n_in,
                              void* d_out, int out_size)
{
    const float* x    = (const float*)d_in[0];
    const float* W_ih = (const float*)d_in[1];
    const float* W_hh = (const float*)d_in[2];
    const float* b_ih = (const float*)d_in[3];
    const float* b_hh = (const float*)d_in[4];
    const float* fc_W = (const float*)d_in[5];
    const float* fc_b = (const float*)d_in[6];
    float* out = (float*)d_out;

    xw_kernel<<<dim3(BATCH / 4, TSTEP / 32), 256>>>(x, W_ih, b_ih, b_hh);
    scan_kernel<<<NCTA, 512>>>(W_hh, fc_W, fc_b, out);
}